// round 7
// baseline (speedup 1.0000x reference)
#include <cuda_runtime.h>
#include <cuda_bf16.h>
#include <cstdint>

// ============================================================================
// Problem constants
// ============================================================================
#define HEAD_DIM   128
#define NUM_HEADS  2
#define KWIN       32
#define KD         4096            // KWIN * HEAD_DIM
#define RESCALE    0.015625f       // (32*128)^-0.5

#define MT      64                 // M tile rows ((w,h) pairs) -> 32 windows
#define WTILE   32                 // windows per block
#define NT      32                 // gate outputs per head
#define KC      64                 // K chunk (fp32 elements) = half token row
#define NITER   (KD / KC)          // 64
#define NSTAGE  3                  // cp.async pipeline depth (3 CTAs/SM)

#define NCOPY   192
#define MAXROWS 65536

// ============================================================================
// Scratch (__device__ globals; allocation-free rule)
// ============================================================================
__device__ __nv_bfloat16 g_gw[NT * KD];            // 256 KB bf16 gate weight
__device__ uint32_t      g_bm[MAXROWS / 32];       // dest-row bitmap

// ============================================================================
// Helpers
// ============================================================================
__device__ __forceinline__ uint32_t smem_u32(const void* p) {
    uint32_t a;
    asm("{ .reg .u64 t; cvta.to.shared.u64 t, %1; cvt.u32.u64 %0, t; }"
        : "=r"(a) : "l"(p));
    return a;
}

__device__ __forceinline__ void cp16(uint32_t dst, const void* src) {
    asm volatile("cp.async.cg.shared.global [%0], [%1], 16;"
                 :: "r"(dst), "l"(src) : "memory");
}
#define CP_COMMIT() asm volatile("cp.async.commit_group;" ::: "memory")
#define CP_WAIT()   asm volatile("cp.async.wait_group %0;" :: "n"(NSTAGE - 2) : "memory")

__device__ __forceinline__ float2 lds64(uint32_t a) {
    float2 v;
    asm volatile("ld.shared.v2.f32 {%0,%1}, [%2];"
                 : "=f"(v.x), "=f"(v.y) : "r"(a));
    return v;
}

__device__ __forceinline__ uint32_t pack2(float2 f) {
    __nv_bfloat162 h = __floats2bfloat162_rn(f.x, f.y);
    return *reinterpret_cast<uint32_t*>(&h);
}

__device__ __forceinline__ uint2 pack_bf16x4(float4 f) {
    __nv_bfloat162 lo = __floats2bfloat162_rn(f.x, f.y);
    __nv_bfloat162 hi = __floats2bfloat162_rn(f.z, f.w);
    uint2 r;
    r.x = *reinterpret_cast<uint32_t*>(&lo);
    r.y = *reinterpret_cast<uint32_t*>(&hi);
    return r;
}

__device__ __forceinline__ void ldmatrix_x4(uint32_t* r, uint32_t addr) {
    asm volatile("ldmatrix.sync.aligned.m8n8.x4.shared.b16 {%0,%1,%2,%3}, [%4];"
                 : "=r"(r[0]), "=r"(r[1]), "=r"(r[2]), "=r"(r[3])
                 : "r"(addr));
}

__device__ __forceinline__ void mma_bf16(float* d, const uint32_t* a,
                                         uint32_t b0, uint32_t b1) {
    asm volatile(
        "mma.sync.aligned.m16n8k16.row.col.f32.bf16.bf16.f32 "
        "{%0,%1,%2,%3}, {%4,%5,%6,%7}, {%8,%9}, {%0,%1,%2,%3};"
        : "+f"(d[0]), "+f"(d[1]), "+f"(d[2]), "+f"(d[3])
        : "r"(a[0]), "r"(a[1]), "r"(a[2]), "r"(a[3]), "r"(b0), "r"(b1));
}

__device__ __forceinline__ float sigf(float x) {
    return 1.0f / (1.0f + __expf(-x * RESCALE));
}

// ============================================================================
// Pre-kernels
// ============================================================================
__global__ void cvt_gw_kernel(const float* __restrict__ gw) {
    int i = blockIdx.x * blockDim.x + threadIdx.x;     // 32768 float4 tasks
    float4 v = reinterpret_cast<const float4*>(gw)[i];
    reinterpret_cast<uint2*>(g_gw)[i] = pack_bf16x4(v);
}

__global__ void zero_bm_kernel(int nwords) {
    int i = blockIdx.x * blockDim.x + threadIdx.x;
    if (i < nwords) g_bm[i] = 0u;
}

__global__ void set_bm_kernel(const int* __restrict__ dest, int W) {
    int i = blockIdx.x * blockDim.x + threadIdx.x;
    if (i < W) {
        int d = dest[i];
        atomicOr(&g_bm[d >> 5], 1u << (d & 31));
    }
}

// ============================================================================
// Fused kernel.
//   Blocks [0, nblk): gather GEMM via 3-stage cp.async pipeline, 3 CTAs/SM.
//     A: fp32 in smem (swizzled 8B granules), converted to bf16 at consume.
//     B: bf16 in smem (from g_gw), ldmatrix.
//   Blocks [nblk, nblk+NCOPY): bitmap-masked copy of cbuf -> out.
// ============================================================================
struct SmemT {
    __align__(256) float          A[NSTAGE][MT * KC];   // 3 x 16 KB fp32
    __align__(256) __nv_bfloat16  B[NSTAGE][NT * KC];   // 3 x  4 KB bf16
    int   widx[WTILE * KWIN];                           //  4 KB
    float g[MT * NT];                                   //  8 KB
    int   dst[WTILE];
};
#define SMEM_BYTES ((int)sizeof(SmemT))

__global__ __launch_bounds__(256, 3)
void fused_kernel(const float* __restrict__ buffer,
                  const float* __restrict__ cbuf,
                  const int*   __restrict__ widx,
                  const int*   __restrict__ dest,
                  float*       __restrict__ out,
                  int W, int Mtot, int nblk, int crows)
{
    extern __shared__ char smraw[];
    SmemT& sm = *reinterpret_cast<SmemT*>(smraw);

    const int tid = threadIdx.x;

    // ---------------- copy blocks ----------------
    if (blockIdx.x >= nblk) {
        int cb  = blockIdx.x - nblk;
        int rpb = (crows + NCOPY - 1) / NCOPY;
        int r0  = cb * rpb;
        int r1  = min(r0 + rpb, crows);
        const float4* src4 = reinterpret_cast<const float4*>(cbuf);
        float4*       dst4 = reinterpret_cast<float4*>(out);
        int rsub = tid >> 6;
        int lane = tid & 63;
        for (int r = r0 + rsub; r < r1; r += 4) {
            if ((g_bm[r >> 5] >> (r & 31)) & 1u) continue;   // dest row: skip
            dst4[(size_t)r * 64 + lane] = src4[(size_t)r * 64 + lane];
        }
        return;
    }

    // ---------------- GEMM blocks ----------------
    const int warp = tid >> 5;
    const int lid  = tid & 31;

    const int w_base = blockIdx.x * WTILE;

    // stage window indices + dest slots (padded windows -> slot 0)
    #pragma unroll
    for (int rep = 0; rep < 4; rep++) {
        int t  = rep * 256 + tid;                      // 1024 entries
        int wl = t >> 5;
        int wg = w_base + wl;
        sm.widx[t] = (wg < W) ? widx[(size_t)wg * KWIN + (t & 31)] : 0;
    }
    if (tid < WTILE) {
        int wg = w_base + tid;
        sm.dst[tid] = (wg < W) ? dest[wg] : 0;
    }
    __syncthreads();

    // ---- cp.async stage issue: A 4 tasks/thread, B 1 task/thread ----
    auto issue_stage = [&](int it) {
        int b     = it % NSTAGE;
        int token = it >> 1;
        int half  = (it & 1) << 6;                     // 0 or 64 fp32
        uint32_t A_base = smem_u32(sm.A[b]);
        uint32_t B_base = smem_u32(sm.B[b]);
        #pragma unroll
        for (int rep = 0; rep < 4; rep++) {
            int t   = rep * 256 + tid;                 // 1024 tasks
            int row = t >> 4;                          // 0..63
            int c   = t & 15;                          // 16B chunk (4 fp32)
            int slot = sm.widx[(row >> 1) * KWIN + token];
            const float* src = buffer
                + ((size_t)slot * (NUM_HEADS * HEAD_DIM)
                   + (row & 1) * HEAD_DIM + half + c * 4);
            uint32_t dst = A_base + row * 256
                + ((uint32_t)((c * 2) ^ ((row & 7) << 2)) << 3);
            cp16(dst, src);
        }
        {
            int row = tid >> 3;                        // 0..31
            int ch  = tid & 7;                         // 16B chunk (8 bf16)
            const __nv_bfloat16* src = g_gw + (size_t)row * KD + it * KC + ch * 8;
            uint32_t dst = B_base + row * 128
                + ((uint32_t)(ch ^ (row & 7)) << 4);
            cp16(dst, src);
        }
        CP_COMMIT();
    };

    // ---- per-warp MMA geometry ----
    const int wm = (warp >> 1) * 16;                   // M rows wm..wm+15
    const int nb = (warp & 1) * 16;                    // N half
    const int gq = lid >> 3;
    const int rr = lid & 7;
    const int c2 = lid & 3;                            // k-pair index

    const int rowA0 = wm + (lid >> 2);
    const int rowA1 = rowA0 + 8;
    const uint32_t sA0 = (uint32_t)((rowA0 & 7) << 2);
    const uint32_t sA1 = (uint32_t)((rowA1 & 7) << 2);

    const int nB  = nb + ((gq >> 1) << 3) + rr;
    const int cB  = gq & 1;
    const uint32_t xB = (uint32_t)(nB & 7);

    float acc[2][4] = {};

    // ---- prologue: fill NSTAGE-1 stages ----
    #pragma unroll
    for (int s = 0; s < NSTAGE - 1; s++) issue_stage(s);

    // ---- mainloop ----
    for (int it = 0; it < NITER; it++) {
        int b = it % NSTAGE;
        CP_WAIT();
        __syncthreads();

        if (it + NSTAGE - 1 < NITER) issue_stage(it + NSTAGE - 1);
        else                         CP_COMMIT();      // keep group count uniform

        uint32_t Ab0 = smem_u32(sm.A[b]) + rowA0 * 256;
        uint32_t Ab1 = smem_u32(sm.A[b]) + rowA1 * 256;
        uint32_t Bb  = smem_u32(sm.B[b]) + nB * 128;

        #pragma unroll
        for (int q = 0; q < 4; q++) {                  // 4 k16 steps per chunk
            uint32_t g0 = (uint32_t)(q * 8 + c2);
            uint32_t g1 = g0 + 4;
            float2 f00 = lds64(Ab0 + ((g0 ^ sA0) << 3));
            float2 f01 = lds64(Ab1 + ((g0 ^ sA1) << 3));
            float2 f10 = lds64(Ab0 + ((g1 ^ sA0) << 3));
            float2 f11 = lds64(Ab1 + ((g1 ^ sA1) << 3));
            uint32_t a[4];
            a[0] = pack2(f00);
            a[1] = pack2(f01);
            a[2] = pack2(f10);
            a[3] = pack2(f11);
            uint32_t bf[4];
            uint32_t chB = ((uint32_t)(q * 2 + cB)) ^ xB;
            ldmatrix_x4(bf, Bb + (chB << 4));
            mma_bf16(acc[0], a, bf[0], bf[1]);
            mma_bf16(acc[1], a, bf[2], bf[3]);
        }
    }

    // ---- gates: sigmoid -> smem ----
    {
        int row0 = wm + (lid >> 2);
        int row1 = row0 + 8;
        #pragma unroll
        for (int j = 0; j < 2; j++) {
            int n0 = nb + j * 8 + (lid & 3) * 2;
            sm.g[row0 * NT + n0]     = sigf(acc[j][0]);
            sm.g[row0 * NT + n0 + 1] = sigf(acc[j][1]);
            sm.g[row1 * NT + n0]     = sigf(acc[j][2]);
            sm.g[row1 * NT + n0 + 1] = sigf(acc[j][3]);
        }
    }
    __syncthreads();

    // ---- gated reduction + scatter (tokens L2-hot) ----
    const int wsub = tid >> 6;
    const int h    = (tid >> 5) & 1;
    const int dq   = tid & 31;

    for (int p = 0; p < 8; p++) {
        int wl = p * 4 + wsub;
        int wg = w_base + wl;
        if (wg >= W) continue;
        const float* gp = sm.g + (wl * 2 + h) * NT;
        const int*   sp = sm.widx + wl * KWIN;
        float4 acc4 = make_float4(0.f, 0.f, 0.f, 0.f);
        #pragma unroll 8
        for (int k = 0; k < KWIN; k++) {
            float gk = gp[k];
            const float4 t4 = *reinterpret_cast<const float4*>(
                buffer + ((size_t)sp[k] * (NUM_HEADS * HEAD_DIM)
                          + h * HEAD_DIM + dq * 4));
            acc4.x += gk * t4.x;
            acc4.y += gk * t4.y;
            acc4.z += gk * t4.z;
            acc4.w += gk * t4.w;
        }
        *reinterpret_cast<float4*>(
            out + ((size_t)sm.dst[wl] * (NUM_HEADS * HEAD_DIM)
                   + h * HEAD_DIM + dq * 4)) = acc4;
    }
}

// ============================================================================
// Launch
// ============================================================================
extern "C" void kernel_launch(void* const* d_in, const int* in_sizes, int n_in,
                              void* d_out, int out_size)
{
    const float* buffer = (const float*)d_in[0];
    const float* cbuf   = (const float*)d_in[1];
    const float* gw     = (const float*)d_in[2];
    const int*   widx   = (const int*)d_in[3];
    const int*   dest   = (const int*)d_in[4];
    int W     = in_sizes[4];
    int crows = out_size / (NUM_HEADS * HEAD_DIM);

    cudaFuncSetAttribute(fused_kernel,
                         cudaFuncAttributeMaxDynamicSharedMemorySize, SMEM_BYTES);

    // gate_weight -> bf16 scratch
    cvt_gw_kernel<<<128, 256>>>(gw);
    // dest bitmap
    int nwords = (crows + 31) / 32;
    zero_bm_kernel<<<(nwords + 255) / 256, 256>>>(nwords);
    if (W > 0) set_bm_kernel<<<(W + 255) / 256, 256>>>(dest, W);

    int Mtot = 2 * W;
    int nblk = (Mtot + MT - 1) / MT;          // GEMM blocks (0 allowed)
    fused_kernel<<<nblk + NCOPY, 256, SMEM_BYTES>>>(
        buffer, cbuf, widx, dest, (float*)d_out, W, Mtot, nblk, crows);
}

// round 8
// speedup vs baseline: 1.0914x; 1.0914x over previous
#include <cuda_runtime.h>
#include <cuda_bf16.h>
#include <cstdint>

// ============================================================================
// Problem constants
// ============================================================================
#define HEAD_DIM   128
#define NUM_HEADS  2
#define KWIN       32
#define KD         4096            // KWIN * HEAD_DIM
#define RESCALE    0.015625f       // (32*128)^-0.5

#define MT      32                 // M tile rows ((w,h) pairs) -> 16 windows
#define WTILE   16                 // windows per block
#define NT      32                 // gate outputs per head
#define KC      64                 // K chunk (fp32 elements) = half token row
#define NITER   (KD / KC)          // 64
#define NSTAGE  4                  // cp.async pipeline depth

#define NCOPY   192
#define MAXROWS 65536

// ============================================================================
// Scratch (__device__ globals; allocation-free rule)
// ============================================================================
__device__ __nv_bfloat16 g_gw[NT * KD];            // 256 KB bf16 gate weight
__device__ uint32_t      g_bm[MAXROWS / 32];       // dest-row bitmap

// ============================================================================
// Helpers
// ============================================================================
__device__ __forceinline__ uint32_t smem_u32(const void* p) {
    uint32_t a;
    asm("{ .reg .u64 t; cvta.to.shared.u64 t, %1; cvt.u32.u64 %0, t; }"
        : "=r"(a) : "l"(p));
    return a;
}

__device__ __forceinline__ void cp16(uint32_t dst, const void* src) {
    asm volatile("cp.async.cg.shared.global [%0], [%1], 16;"
                 :: "r"(dst), "l"(src) : "memory");
}
#define CP_COMMIT() asm volatile("cp.async.commit_group;" ::: "memory")
#define CP_WAIT()   asm volatile("cp.async.wait_group %0;" :: "n"(NSTAGE - 2) : "memory")

__device__ __forceinline__ float2 lds64(uint32_t a) {
    float2 v;
    asm volatile("ld.shared.v2.f32 {%0,%1}, [%2];"
                 : "=f"(v.x), "=f"(v.y) : "r"(a));
    return v;
}

__device__ __forceinline__ uint32_t pack2(float2 f) {
    __nv_bfloat162 h = __floats2bfloat162_rn(f.x, f.y);
    return *reinterpret_cast<uint32_t*>(&h);
}

__device__ __forceinline__ uint2 pack_bf16x4(float4 f) {
    __nv_bfloat162 lo = __floats2bfloat162_rn(f.x, f.y);
    __nv_bfloat162 hi = __floats2bfloat162_rn(f.z, f.w);
    uint2 r;
    r.x = *reinterpret_cast<uint32_t*>(&lo);
    r.y = *reinterpret_cast<uint32_t*>(&hi);
    return r;
}

__device__ __forceinline__ void ldmatrix_x2(uint32_t* r, uint32_t addr) {
    asm volatile("ldmatrix.sync.aligned.m8n8.x2.shared.b16 {%0,%1}, [%2];"
                 : "=r"(r[0]), "=r"(r[1]) : "r"(addr));
}

__device__ __forceinline__ void mma_bf16(float* d, const uint32_t* a,
                                         uint32_t b0, uint32_t b1) {
    asm volatile(
        "mma.sync.aligned.m16n8k16.row.col.f32.bf16.bf16.f32 "
        "{%0,%1,%2,%3}, {%4,%5,%6,%7}, {%8,%9}, {%0,%1,%2,%3};"
        : "+f"(d[0]), "+f"(d[1]), "+f"(d[2]), "+f"(d[3])
        : "r"(a[0]), "r"(a[1]), "r"(a[2]), "r"(a[3]), "r"(b0), "r"(b1));
}

__device__ __forceinline__ float sigf(float x) {
    return 1.0f / (1.0f + __expf(-x * RESCALE));
}

// ============================================================================
// Pre-kernels
// ============================================================================
__global__ void cvt_gw_kernel(const float* __restrict__ gw) {
    int i = blockIdx.x * blockDim.x + threadIdx.x;     // 32768 float4 tasks
    float4 v = reinterpret_cast<const float4*>(gw)[i];
    reinterpret_cast<uint2*>(g_gw)[i] = pack_bf16x4(v);
}

__global__ void zero_bm_kernel(int nwords) {
    int i = blockIdx.x * blockDim.x + threadIdx.x;
    if (i < nwords) g_bm[i] = 0u;
}

__global__ void set_bm_kernel(const int* __restrict__ dest, int W) {
    int i = blockIdx.x * blockDim.x + threadIdx.x;
    if (i < W) {
        int d = dest[i];
        atomicOr(&g_bm[d >> 5], 1u << (d & 31));
    }
}

// ============================================================================
// Fused kernel.
//   Blocks [0, nblk): gather GEMM, MT=32, 4-stage cp.async, 4 CTAs/SM target.
//     A: fp32 in smem (swizzled 8B granules), cvt to bf16 at consume.
//     B: bf16 in smem (from g_gw), ldmatrix.x2 per warp n8.
//   Blocks [nblk, nblk+NCOPY): bitmap-masked copy of cbuf -> out.
// ============================================================================
struct SmemT {
    __align__(256) float          A[NSTAGE][MT * KC];   // 4 x 8 KB fp32
    __align__(256) __nv_bfloat16  B[NSTAGE][NT * KC];   // 4 x 4 KB bf16
    int   widx[WTILE * KWIN];                           //  2 KB
    float g[MT * NT];                                   //  4 KB
    int   dst[WTILE];
};
#define SMEM_BYTES ((int)sizeof(SmemT))

__global__ __launch_bounds__(256, 4)
void fused_kernel(const float* __restrict__ buffer,
                  const float* __restrict__ cbuf,
                  const int*   __restrict__ widx,
                  const int*   __restrict__ dest,
                  float*       __restrict__ out,
                  int W, int Mtot, int nblk, int crows)
{
    extern __shared__ char smraw[];
    SmemT& sm = *reinterpret_cast<SmemT*>(smraw);

    const int tid = threadIdx.x;

    // ---------------- copy blocks ----------------
    if (blockIdx.x >= nblk) {
        int cb  = blockIdx.x - nblk;
        int rpb = (crows + NCOPY - 1) / NCOPY;
        int r0  = cb * rpb;
        int r1  = min(r0 + rpb, crows);
        const float4* src4 = reinterpret_cast<const float4*>(cbuf);
        float4*       dst4 = reinterpret_cast<float4*>(out);
        int rsub = tid >> 6;
        int lane = tid & 63;
        for (int r = r0 + rsub; r < r1; r += 4) {
            if ((g_bm[r >> 5] >> (r & 31)) & 1u) continue;   // dest row: skip
            dst4[(size_t)r * 64 + lane] = src4[(size_t)r * 64 + lane];
        }
        return;
    }

    // ---------------- GEMM blocks ----------------
    const int warp = tid >> 5;
    const int lid  = tid & 31;

    const int w_base = blockIdx.x * WTILE;

    // stage window indices + dest slots (padded windows -> slot 0)
    #pragma unroll
    for (int rep = 0; rep < 2; rep++) {
        int t  = rep * 256 + tid;                      // 512 entries
        int wl = t >> 5;
        int wg = w_base + wl;
        sm.widx[t] = (wg < W) ? widx[(size_t)wg * KWIN + (t & 31)] : 0;
    }
    if (tid < WTILE) {
        int wg = w_base + tid;
        sm.dst[tid] = (wg < W) ? dest[wg] : 0;
    }
    __syncthreads();

    // ---- cp.async stage issue: A 2 tasks/thread, B 1 task/thread ----
    auto issue_stage = [&](int it) {
        int b     = it & (NSTAGE - 1);
        int token = it >> 1;
        int half  = (it & 1) << 6;                     // 0 or 64 fp32
        uint32_t A_base = smem_u32(sm.A[b]);
        uint32_t B_base = smem_u32(sm.B[b]);
        #pragma unroll
        for (int rep = 0; rep < 2; rep++) {
            int t   = rep * 256 + tid;                 // 512 tasks
            int row = t >> 4;                          // 0..31
            int c   = t & 15;                          // 16B chunk (4 fp32)
            int slot = sm.widx[(row >> 1) * KWIN + token];
            const float* src = buffer
                + ((size_t)slot * (NUM_HEADS * HEAD_DIM)
                   + (row & 1) * HEAD_DIM + half + c * 4);
            uint32_t dst = A_base + row * 256
                + ((uint32_t)((c * 2) ^ ((row & 7) << 2)) << 3);
            cp16(dst, src);
        }
        {
            int row = tid >> 3;                        // 0..31
            int ch  = tid & 7;                         // 16B chunk (8 bf16)
            const __nv_bfloat16* src = g_gw + (size_t)row * KD + it * KC + ch * 8;
            uint32_t dst = B_base + row * 128
                + ((uint32_t)(ch ^ (row & 7)) << 4);
            cp16(dst, src);
        }
        CP_COMMIT();
    };

    // ---- per-warp MMA geometry: warp = (mblk, n8) ----
    const int wm = (warp >> 2) * 16;                   // 0 or 16
    const int n8 = (warp & 3) * 8;                     // 0,8,16,24
    const int c2 = lid & 3;                            // k-pair index

    const int rowA0 = wm + (lid >> 2);
    const int rowA1 = rowA0 + 8;
    const uint32_t sA0 = (uint32_t)((rowA0 & 7) << 2);
    const uint32_t sA1 = (uint32_t)((rowA1 & 7) << 2);

    const int nB  = n8 + (lid & 7);                    // lanes 0-15 feed ldmatrix.x2
    const int ckB = (lid >> 3) & 1;
    const uint32_t xB = (uint32_t)(nB & 7);

    float acc[4] = {};

    // ---- prologue: fill NSTAGE-1 stages ----
    #pragma unroll
    for (int s = 0; s < NSTAGE - 1; s++) issue_stage(s);

    // ---- mainloop ----
    for (int it = 0; it < NITER; it++) {
        int b = it & (NSTAGE - 1);
        CP_WAIT();
        __syncthreads();

        if (it + NSTAGE - 1 < NITER) issue_stage(it + NSTAGE - 1);
        else                         CP_COMMIT();      // keep group count uniform

        uint32_t Ab0 = smem_u32(sm.A[b]) + rowA0 * 256;
        uint32_t Ab1 = smem_u32(sm.A[b]) + rowA1 * 256;
        uint32_t Bb  = smem_u32(sm.B[b]) + nB * 128;

        #pragma unroll
        for (int q = 0; q < 4; q++) {                  // 4 k16 steps per chunk
            uint32_t g0 = (uint32_t)(q * 8 + c2);
            uint32_t g1 = g0 + 4;
            uint32_t a[4];
            a[0] = pack2(lds64(Ab0 + ((g0 ^ sA0) << 3)));
            a[1] = pack2(lds64(Ab1 + ((g0 ^ sA1) << 3)));
            a[2] = pack2(lds64(Ab0 + ((g1 ^ sA0) << 3)));
            a[3] = pack2(lds64(Ab1 + ((g1 ^ sA1) << 3)));
            uint32_t bf[2];
            uint32_t chB = ((uint32_t)(q * 2 + ckB)) ^ xB;
            ldmatrix_x2(bf, Bb + (chB << 4));
            mma_bf16(acc, a, bf[0], bf[1]);
        }
    }

    // ---- gates: sigmoid -> smem ----
    {
        int row0 = wm + (lid >> 2);
        int row1 = row0 + 8;
        int n0   = n8 + (lid & 3) * 2;
        sm.g[row0 * NT + n0]     = sigf(acc[0]);
        sm.g[row0 * NT + n0 + 1] = sigf(acc[1]);
        sm.g[row1 * NT + n0]     = sigf(acc[2]);
        sm.g[row1 * NT + n0 + 1] = sigf(acc[3]);
    }
    __syncthreads();

    // ---- gated reduction + scatter (tokens L2-hot) ----
    const int wsub = tid >> 6;
    const int h    = (tid >> 5) & 1;
    const int dq   = tid & 31;

    for (int p = 0; p < 4; p++) {
        int wl = p * 4 + wsub;
        int wg = w_base + wl;
        if (wg >= W) continue;
        const float* gp = sm.g + (wl * 2 + h) * NT;
        const int*   sp = sm.widx + wl * KWIN;
        float4 acc4 = make_float4(0.f, 0.f, 0.f, 0.f);
        #pragma unroll 8
        for (int k = 0; k < KWIN; k++) {
            float gk = gp[k];
            const float4 t4 = *reinterpret_cast<const float4*>(
                buffer + ((size_t)sp[k] * (NUM_HEADS * HEAD_DIM)
                          + h * HEAD_DIM + dq * 4));
            acc4.x += gk * t4.x;
            acc4.y += gk * t4.y;
            acc4.z += gk * t4.z;
            acc4.w += gk * t4.w;
        }
        *reinterpret_cast<float4*>(
            out + ((size_t)sm.dst[wl] * (NUM_HEADS * HEAD_DIM)
                   + h * HEAD_DIM + dq * 4)) = acc4;
    }
}

// ============================================================================
// Launch
// ============================================================================
extern "C" void kernel_launch(void* const* d_in, const int* in_sizes, int n_in,
                              void* d_out, int out_size)
{
    const float* buffer = (const float*)d_in[0];
    const float* cbuf   = (const float*)d_in[1];
    const float* gw     = (const float*)d_in[2];
    const int*   widx   = (const int*)d_in[3];
    const int*   dest   = (const int*)d_in[4];
    int W     = in_sizes[4];
    int crows = out_size / (NUM_HEADS * HEAD_DIM);

    cudaFuncSetAttribute(fused_kernel,
                         cudaFuncAttributeMaxDynamicSharedMemorySize, SMEM_BYTES);

    // gate_weight -> bf16 scratch
    cvt_gw_kernel<<<128, 256>>>(gw);
    // dest bitmap
    int nwords = (crows + 31) / 32;
    zero_bm_kernel<<<(nwords + 255) / 256, 256>>>(nwords);
    if (W > 0) set_bm_kernel<<<(W + 255) / 256, 256>>>(dest, W);

    int Mtot = 2 * W;
    int nblk = (Mtot + MT - 1) / MT;          // GEMM blocks (0 allowed)
    fused_kernel<<<nblk + NCOPY, 256, SMEM_BYTES>>>(
        buffer, cbuf, widx, dest, (float*)d_out, W, Mtot, nblk, crows);
}